// round 5
// baseline (speedup 1.0000x reference)
#include <cuda_runtime.h>
#include <cuda_bf16.h>
#include <math.h>

// Problem constants
constexpr int B_   = 256;
constexpr int L_   = 100;
constexpr int C_   = 55;
constexpr int D_   = 512;
constexpr int H_   = 8;
constexpr int NL_  = 3;
constexpr int DFF_ = 64;
constexpr int DK_  = D_ / H_;      // 64
constexpr int BL_  = B_ * L_;      // 25600
constexpr int KC_  = 3 * C_;       // 165 (conv im2col K)

// ---------------- scratch (static device allocations are allowed) ----------
__device__ float g_h [BL_ * D_];
__device__ float g_q [BL_ * D_];
__device__ float g_k [BL_ * D_];
__device__ float g_v [BL_ * D_];
__device__ float g_o [BL_ * D_];
__device__ float g_y [BL_ * DFF_];
__device__ float g_xg[BL_ * KC_];

// ---------------- im2col gather for circular conv1d k=3 --------------------
__global__ void __launch_bounds__(256) gather_kernel(const float* __restrict__ x) {
    int idx = blockIdx.x * blockDim.x + threadIdx.x;
    const int total = BL_ * KC_;
    if (idx >= total) return;
    int kk = idx % KC_;
    int bl = idx / KC_;
    int c = kk / 3, j = kk % 3;
    int b = bl / L_, l = bl % L_;
    int ls = l - 1 + j;
    if (ls < 0) ls += L_;
    if (ls >= L_) ls -= L_;
    g_xg[idx] = x[((size_t)b * L_ + ls) * C_ + c];
}

// ---------------- generic SGEMM: C [M,N] (+)= A[M,K] @ W[N,K]^T + bias ------
// Optional: positional-embedding add (pe[(m%L)*N + n]), exact GELU, beta=1.
template <bool BETA1, bool GELU_, bool PE>
__global__ void __launch_bounds__(256) gemm_kernel(
    int M, int N, int K,
    const float* __restrict__ A,
    const float* __restrict__ W,
    const float* __restrict__ bias,
    float* __restrict__ C,
    const float* __restrict__ pe)
{
    constexpr int BM = 128, BN = 64, BK = 16, TM = 8, TN = 4;
    __shared__ float As[BK][BM + 4];
    __shared__ float Ws[BK][BN + 4];

    const int tid = threadIdx.x;
    const int tx  = tid & 15;          // 16 col-groups of TN=4
    const int ty  = tid >> 4;          // 16 row-groups of TM=8
    const int rowBase = blockIdx.y * BM;
    const int colBase = blockIdx.x * BN;

    float acc[TM][TN];
    #pragma unroll
    for (int i = 0; i < TM; ++i)
        #pragma unroll
        for (int j = 0; j < TN; ++j) acc[i][j] = 0.f;

    for (int k0 = 0; k0 < K; k0 += BK) {
        // load A tile (BM x BK) -> As[k][m]
        for (int e = tid; e < BM * BK; e += 256) {
            int r = e >> 4, c = e & 15;
            int gr = rowBase + r, gc = k0 + c;
            As[c][r] = (gr < M && gc < K) ? A[(size_t)gr * K + gc] : 0.f;
        }
        // load W tile (BN x BK) -> Ws[k][n]
        for (int e = tid; e < BN * BK; e += 256) {
            int r = e >> 4, c = e & 15;
            int gr = colBase + r, gc = k0 + c;
            Ws[c][r] = (gr < N && gc < K) ? W[(size_t)gr * K + gc] : 0.f;
        }
        __syncthreads();

        #pragma unroll
        for (int kk = 0; kk < BK; ++kk) {
            float af[TM], wf[TN];
            #pragma unroll
            for (int i = 0; i < TM; ++i) af[i] = As[kk][ty * TM + i];
            #pragma unroll
            for (int j = 0; j < TN; ++j) wf[j] = Ws[kk][tx * TN + j];
            #pragma unroll
            for (int i = 0; i < TM; ++i)
                #pragma unroll
                for (int j = 0; j < TN; ++j)
                    acc[i][j] = fmaf(af[i], wf[j], acc[i][j]);
        }
        __syncthreads();
    }

    #pragma unroll
    for (int i = 0; i < TM; ++i) {
        int r = rowBase + ty * TM + i;
        if (r >= M) continue;
        #pragma unroll
        for (int j = 0; j < TN; ++j) {
            int c = colBase + tx * TN + j;
            if (c >= N) continue;
            float v = acc[i][j];
            if (bias) v += bias[c];
            if (PE)   v += pe[(size_t)(r % L_) * N + c];
            if (GELU_) v = 0.5f * v * (1.f + erff(v * 0.70710678118654752f));
            size_t off = (size_t)r * N + c;
            if (BETA1) v += C[off];
            C[off] = v;
        }
    }
}

// ---------------- attention: one CTA per (b, h) -----------------------------
// S = softmax(scale * q k^T), o = S v.  All tiles (100x64) resident in SMEM.
constexpr int S_STRIDE = 104;                       // padded row stride for S
constexpr int ATTN_SMEM_FLOATS = L_ * S_STRIDE      // S   [100][104]
                               + L_ * DK_           // qs  [100][64]
                               + DK_ * L_;          // kst [64][100] (reused for v)
constexpr int ATTN_SMEM_BYTES = ATTN_SMEM_FLOATS * 4;   // 92800 B

__global__ void __launch_bounds__(256) attn_kernel(
    const float* __restrict__ q,
    const float* __restrict__ k,
    const float* __restrict__ v,
    float* __restrict__ o)
{
    extern __shared__ float sm[];
    float* S   = sm;                          // [100][104]
    float* qs  = sm + L_ * S_STRIDE;          // [100][64]
    float* kst = qs + L_ * DK_;               // [64][100], later vs [100][64]

    const int b = blockIdx.x / H_;
    const int h = blockIdx.x % H_;
    const float* qb = q + ((size_t)b * L_) * D_ + h * DK_;
    const float* kb = k + ((size_t)b * L_) * D_ + h * DK_;
    const float* vb = v + ((size_t)b * L_) * D_ + h * DK_;
    float*       ob = o + ((size_t)b * L_) * D_ + h * DK_;
    const int tid = threadIdx.x;

    // load q row-major, k transposed [e][j]
    for (int idx = tid; idx < L_ * DK_; idx += blockDim.x) {
        int r = idx / DK_, e = idx % DK_;
        qs [r * DK_ + e] = qb[(size_t)r * D_ + e];
        kst[e * L_  + r] = kb[(size_t)r * D_ + e];
    }
    __syncthreads();

    // phase 1: scores (4 j's per thread, vectorized k reads)
    const float scale = 0.125f;  // 1/sqrt(64)
    for (int p = tid; p < L_ * (L_ / 4); p += blockDim.x) {
        int i  = p / (L_ / 4);
        int j4 = (p % (L_ / 4)) * 4;
        float s0 = 0.f, s1 = 0.f, s2 = 0.f, s3 = 0.f;
        #pragma unroll 8
        for (int e = 0; e < DK_; ++e) {
            float qv = qs[i * DK_ + e];
            const float4 kv = *reinterpret_cast<const float4*>(kst + e * L_ + j4);
            s0 = fmaf(qv, kv.x, s0);
            s1 = fmaf(qv, kv.y, s1);
            s2 = fmaf(qv, kv.z, s2);
            s3 = fmaf(qv, kv.w, s3);
        }
        float4 sv = make_float4(s0 * scale, s1 * scale, s2 * scale, s3 * scale);
        *reinterpret_cast<float4*>(S + i * S_STRIDE + j4) = sv;
    }
    __syncthreads();

    // reuse kst region as v [j][64]
    float* vs = kst;
    for (int idx = tid; idx < L_ * DK_; idx += blockDim.x) {
        int r = idx / DK_, e = idx % DK_;
        vs[r * DK_ + e] = vb[(size_t)r * D_ + e];
    }
    // softmax: one warp per row
    {
        int warp = tid >> 5, lane = tid & 31;
        for (int i = warp; i < L_; i += (int)(blockDim.x >> 5)) {
            float* Sr = S + i * S_STRIDE;
            float m = -1e30f;
            for (int j = lane; j < L_; j += 32) m = fmaxf(m, Sr[j]);
            #pragma unroll
            for (int off = 16; off; off >>= 1)
                m = fmaxf(m, __shfl_xor_sync(0xffffffff, m, off));
            float sum = 0.f;
            for (int j = lane; j < L_; j += 32) {
                float ev = __expf(Sr[j] - m);
                Sr[j] = ev;
                sum += ev;
            }
            #pragma unroll
            for (int off = 16; off; off >>= 1)
                sum += __shfl_xor_sync(0xffffffff, sum, off);
            float inv = 1.f / sum;
            for (int j = lane; j < L_; j += 32) Sr[j] *= inv;
        }
    }
    __syncthreads();

    // phase 2: o = S @ v
    for (int idx = tid; idx < L_ * DK_; idx += blockDim.x) {
        int i = idx / DK_, d = idx % DK_;
        const float* Sr = S + i * S_STRIDE;
        float acc = 0.f;
        #pragma unroll 4
        for (int j = 0; j < L_; ++j)
            acc = fmaf(Sr[j], vs[j * DK_ + d], acc);
        ob[(size_t)i * D_ + d] = acc;
    }
}

// ---------------- host-side launch helpers ---------------------------------
static void launch_gemm(const float* A, const float* W, const float* bias,
                        float* C, int M, int N, int K, int mode,
                        const float* pe = nullptr) {
    dim3 grid((N + 63) / 64, (M + 127) / 128);
    switch (mode) {
        case 0: gemm_kernel<false, false, false><<<grid, 256>>>(M, N, K, A, W, bias, C, nullptr); break;
        case 1: gemm_kernel<true,  false, false><<<grid, 256>>>(M, N, K, A, W, bias, C, nullptr); break;
        case 2: gemm_kernel<false, true,  false><<<grid, 256>>>(M, N, K, A, W, bias, C, nullptr); break;
        default: gemm_kernel<false, false, true ><<<grid, 256>>>(M, N, K, A, W, bias, C, pe);     break;
    }
}

extern "C" void kernel_launch(void* const* d_in, const int* in_sizes, int n_in,
                              void* d_out, int out_size) {
    (void)in_sizes; (void)n_in; (void)out_size;
    const float* x     = (const float*)d_in[0];
    const float* tok_w = (const float*)d_in[1];
    const float* pe    = (const float*)d_in[2];
    const float* Wq    = (const float*)d_in[3];
    const float* bq    = (const float*)d_in[4];
    const float* Wk    = (const float*)d_in[5];
    const float* bk    = (const float*)d_in[6];
    const float* Wv    = (const float*)d_in[7];
    const float* bv    = (const float*)d_in[8];
    // d_in[9] = Wsig, d_in[10] = bsig: the Gaussian-prior branch never feeds
    // the module output -> intentionally skipped.
    const float* Wo    = (const float*)d_in[11];
    const float* bo    = (const float*)d_in[12];
    const float* W1    = (const float*)d_in[13];
    const float* b1    = (const float*)d_in[14];
    const float* W2    = (const float*)d_in[15];
    const float* b2    = (const float*)d_in[16];
    const float* pw    = (const float*)d_in[17];
    const float* pb    = (const float*)d_in[18];
    float* out = (float*)d_out;

    float *h, *q, *k, *v, *o, *y, *xg;
    cudaGetSymbolAddress((void**)&h,  g_h);
    cudaGetSymbolAddress((void**)&q,  g_q);
    cudaGetSymbolAddress((void**)&k,  g_k);
    cudaGetSymbolAddress((void**)&v,  g_v);
    cudaGetSymbolAddress((void**)&o,  g_o);
    cudaGetSymbolAddress((void**)&y,  g_y);
    cudaGetSymbolAddress((void**)&xg, g_xg);

    cudaFuncSetAttribute(attn_kernel,
                         cudaFuncAttributeMaxDynamicSharedMemorySize,
                         ATTN_SMEM_BYTES);

    // token embedding: im2col gather + GEMM (+ positional embedding epilogue)
    gather_kernel<<<(BL_ * KC_ + 255) / 256, 256>>>(x);
    launch_gemm(xg, tok_w, nullptr, h, BL_, D_, KC_, 3, pe);

    for (int l = 0; l < NL_; ++l) {
        const size_t wOff = (size_t)l * D_ * D_;
        launch_gemm(h, Wq + wOff, bq + (size_t)l * D_, q, BL_, D_, D_, 0);
        launch_gemm(h, Wk + wOff, bk + (size_t)l * D_, k, BL_, D_, D_, 0);
        launch_gemm(h, Wv + wOff, bv + (size_t)l * D_, v, BL_, D_, D_, 0);

        attn_kernel<<<B_ * H_, 256, ATTN_SMEM_BYTES>>>(q, k, v, o);

        // h += o @ Wo^T + bo
        launch_gemm(o, Wo + wOff, bo + (size_t)l * D_, h, BL_, D_, D_, 1);
        // y = gelu(h @ W1^T + b1)
        launch_gemm(h, W1 + (size_t)l * DFF_ * D_, b1 + (size_t)l * DFF_,
                    y, BL_, DFF_, D_, 2);
        // h += y @ W2^T + b2
        launch_gemm(y, W2 + (size_t)l * D_ * DFF_, b2 + (size_t)l * D_,
                    h, BL_, D_, DFF_, 1);
    }

    // final projection -> output [B, L, C]
    launch_gemm(h, pw, pb, out, BL_, C_, D_, 0);
}

// round 6
// speedup vs baseline: 2.2555x; 2.2555x over previous
#include <cuda_runtime.h>
#include <cuda_bf16.h>
#include <math.h>
#include <stdint.h>

// Problem constants
constexpr int B_   = 256;
constexpr int L_   = 100;
constexpr int C_   = 55;
constexpr int D_   = 512;
constexpr int H_   = 8;
constexpr int NL_  = 3;
constexpr int DFF_ = 64;
constexpr int DK_  = D_ / H_;      // 64
constexpr int BL_  = B_ * L_;      // 25600
constexpr int KC_  = 3 * C_;       // 165 (conv im2col K)
constexpr int KCP_ = 192;          // padded to multiple of 32 (and 16B-aligned)

// ---------------- scratch (static device allocations) ----------------------
__device__ float g_h [BL_ * D_];
__device__ float g_q [BL_ * D_];
__device__ float g_k [BL_ * D_];
__device__ float g_v [BL_ * D_];
__device__ float g_o [BL_ * D_];
__device__ float g_y [BL_ * DFF_];
__device__ float g_xg[BL_ * KCP_];
__device__ float g_wp[D_ * KCP_];

// ---------------- im2col gather (padded, zero-filled) -----------------------
__global__ void __launch_bounds__(256) gather_kernel(const float* __restrict__ x) {
    int idx = blockIdx.x * blockDim.x + threadIdx.x;
    const int total = BL_ * KCP_;
    if (idx >= total) return;
    int kk = idx % KCP_;
    int bl = idx / KCP_;
    float val = 0.f;
    if (kk < KC_) {
        int c = kk / 3, j = kk % 3;
        int b = bl / L_, l = bl % L_;
        int ls = l - 1 + j;
        if (ls < 0) ls += L_;
        if (ls >= L_) ls -= L_;
        val = x[((size_t)b * L_ + ls) * C_ + c];
    }
    g_xg[idx] = val;
}

// pack tok_w [D][165] -> [D][192] zero-padded
__global__ void __launch_bounds__(256) packw_kernel(const float* __restrict__ w) {
    int idx = blockIdx.x * blockDim.x + threadIdx.x;
    const int total = D_ * KCP_;
    if (idx >= total) return;
    int kk = idx % KCP_;
    int r  = idx / KCP_;
    g_wp[idx] = (kk < KC_) ? w[(size_t)r * KC_ + kk] : 0.f;
}

// ---------------- tf32 helpers ----------------------------------------------
__device__ __forceinline__ uint32_t f2tf(float f) {
    uint32_t u;
    asm("cvt.rna.tf32.f32 %0, %1;" : "=r"(u) : "f"(f));
    return u;
}

// ---------------- tf32 tensor-core GEMM -------------------------------------
// C [M,N] (+)= A[M,K] @ W[N,K]^T + bias.  MODE: 0 plain, 1 beta=1 (C += ...),
// 2 GELU epilogue, 3 positional-embedding epilogue.
// Requirements: M % 128 == 0, K % 32 == 0, A/W rows 16B-aligned.
template<int BN, int MODE>
__global__ void __launch_bounds__(256) mma_gemm(
    int M, int N, int K,
    const float* __restrict__ A,
    const float* __restrict__ W,
    const float* __restrict__ bias,
    float* __restrict__ Cp,
    const float* __restrict__ pe)
{
    constexpr int BM = 128, BK = 32;
    constexpr int WARPS_N = (BN == 128) ? 4 : 2;
    constexpr int WARPS_M = 8 / WARPS_N;
    constexpr int WM = BM / WARPS_M;     // 64 (BN=128) or 32 (BN=64)
    constexpr int WN = BN / WARPS_N;     // 32
    constexpr int MT = WM / 16;          // 4 or 2
    constexpr int NT = WN / 8;           // 4
    constexpr int STR = BK + 4;          // 36 -> conflict-free fragment loads
    constexpr int ALOADS = BM * BK / 4 / 256;   // 4 float4 per thread
    constexpr int BLOADS = BN * BK / 4 / 256;   // 4 or 2

    __shared__ uint32_t As[BM * STR];
    __shared__ uint32_t Bs[BN * STR];

    const int tid  = threadIdx.x;
    const int warp = tid >> 5, lane = tid & 31;
    const int wm = (warp / WARPS_N) * WM;
    const int wn = (warp % WARPS_N) * WN;
    const int g  = lane >> 2;    // 0..7
    const int tg = lane & 3;     // 0..3
    const int rowBase = blockIdx.y * BM;
    const int colBase = blockIdx.x * BN;

    float c[MT][NT][4];
    #pragma unroll
    for (int mt = 0; mt < MT; ++mt)
        #pragma unroll
        for (int nt = 0; nt < NT; ++nt)
            #pragma unroll
            for (int j = 0; j < 4; ++j) c[mt][nt][j] = 0.f;

    float4 aR[ALOADS], bR[BLOADS];

    auto loadG = [&](int k0) {
        #pragma unroll
        for (int i = 0; i < ALOADS; ++i) {
            int f = tid + i * 256;
            int r = f >> 3, cc = (f & 7) * 4;
            aR[i] = *reinterpret_cast<const float4*>(
                A + (size_t)(rowBase + r) * K + k0 + cc);
        }
        #pragma unroll
        for (int i = 0; i < BLOADS; ++i) {
            int f = tid + i * 256;
            int r = f >> 3, cc = (f & 7) * 4;
            int gr = colBase + r;
            if (gr < N)
                bR[i] = *reinterpret_cast<const float4*>(
                    W + (size_t)gr * K + k0 + cc);
            else
                bR[i] = make_float4(0.f, 0.f, 0.f, 0.f);
        }
    };

    auto storeS = [&]() {
        #pragma unroll
        for (int i = 0; i < ALOADS; ++i) {
            int f = tid + i * 256;
            int r = f >> 3, cc = (f & 7) * 4;
            uint32_t* p = &As[r * STR + cc];
            p[0] = f2tf(aR[i].x); p[1] = f2tf(aR[i].y);
            p[2] = f2tf(aR[i].z); p[3] = f2tf(aR[i].w);
        }
        #pragma unroll
        for (int i = 0; i < BLOADS; ++i) {
            int f = tid + i * 256;
            int r = f >> 3, cc = (f & 7) * 4;
            uint32_t* p = &Bs[r * STR + cc];
            p[0] = f2tf(bR[i].x); p[1] = f2tf(bR[i].y);
            p[2] = f2tf(bR[i].z); p[3] = f2tf(bR[i].w);
        }
    };

    auto compute = [&]() {
        #pragma unroll
        for (int ks = 0; ks < 4; ++ks) {
            const int kbase = ks * 8 + tg;
            uint32_t af[MT][4], bf[NT][2];
            #pragma unroll
            for (int mt = 0; mt < MT; ++mt) {
                int r0 = wm + mt * 16 + g;
                af[mt][0] = As[r0 * STR + kbase];
                af[mt][1] = As[(r0 + 8) * STR + kbase];
                af[mt][2] = As[r0 * STR + kbase + 4];
                af[mt][3] = As[(r0 + 8) * STR + kbase + 4];
            }
            #pragma unroll
            for (int nt = 0; nt < NT; ++nt) {
                int n0 = wn + nt * 8 + g;
                bf[nt][0] = Bs[n0 * STR + kbase];
                bf[nt][1] = Bs[n0 * STR + kbase + 4];
            }
            #pragma unroll
            for (int mt = 0; mt < MT; ++mt)
                #pragma unroll
                for (int nt = 0; nt < NT; ++nt)
                    asm volatile(
                        "mma.sync.aligned.m16n8k8.row.col.f32.tf32.tf32.f32 "
                        "{%0,%1,%2,%3}, {%4,%5,%6,%7}, {%8,%9}, {%0,%1,%2,%3};\n"
                        : "+f"(c[mt][nt][0]), "+f"(c[mt][nt][1]),
                          "+f"(c[mt][nt][2]), "+f"(c[mt][nt][3])
                        : "r"(af[mt][0]), "r"(af[mt][1]),
                          "r"(af[mt][2]), "r"(af[mt][3]),
                          "r"(bf[nt][0]), "r"(bf[nt][1]));
        }
    };

    loadG(0);
    storeS();
    __syncthreads();
    const int nIter = K / BK;
    for (int it = 0; it < nIter; ++it) {
        if (it + 1 < nIter) loadG((it + 1) * BK);
        compute();
        if (it + 1 < nIter) {
            __syncthreads();
            storeS();
            __syncthreads();
        }
    }

    // epilogue
    #pragma unroll
    for (int mt = 0; mt < MT; ++mt) {
        #pragma unroll
        for (int nt = 0; nt < NT; ++nt) {
            int r0 = rowBase + wm + mt * 16 + g;
            int c0 = colBase + wn + nt * 8 + tg * 2;
            #pragma unroll
            for (int half = 0; half < 2; ++half) {
                int r = r0 + half * 8;
                #pragma unroll
                for (int jj = 0; jj < 2; ++jj) {
                    int cc = c0 + jj;
                    if (cc >= N) continue;
                    float v = c[mt][nt][half * 2 + jj];
                    if (bias) v += bias[cc];
                    if (MODE == 3) v += pe[(size_t)(r % L_) * N + cc];
                    if (MODE == 2) v = 0.5f * v * (1.f + erff(v * 0.70710678118654752f));
                    size_t off = (size_t)r * N + cc;
                    if (MODE == 1) v += Cp[off];
                    Cp[off] = v;
                }
            }
        }
    }
}

// ---------------- attention: one CTA per (b, h) -----------------------------
constexpr int S_STRIDE = 104;
constexpr int ATTN_SMEM_FLOATS = L_ * S_STRIDE + L_ * DK_ + DK_ * L_;
constexpr int ATTN_SMEM_BYTES  = ATTN_SMEM_FLOATS * 4;   // 92800 B

__global__ void __launch_bounds__(256) attn_kernel(
    const float* __restrict__ q,
    const float* __restrict__ k,
    const float* __restrict__ v,
    float* __restrict__ o)
{
    extern __shared__ float sm[];
    float* S   = sm;                          // [100][104]
    float* qs  = sm + L_ * S_STRIDE;          // [100][64]
    float* kst = qs + L_ * DK_;               // [64][100] (reused for v)

    const int b = blockIdx.x / H_;
    const int h = blockIdx.x % H_;
    const float* qb = q + ((size_t)b * L_) * D_ + h * DK_;
    const float* kb = k + ((size_t)b * L_) * D_ + h * DK_;
    const float* vb = v + ((size_t)b * L_) * D_ + h * DK_;
    float*       ob = o + ((size_t)b * L_) * D_ + h * DK_;
    const int tid = threadIdx.x;

    for (int idx = tid; idx < L_ * DK_; idx += blockDim.x) {
        int r = idx / DK_, e = idx % DK_;
        qs [r * DK_ + e] = qb[(size_t)r * D_ + e];
        kst[e * L_  + r] = kb[(size_t)r * D_ + e];
    }
    __syncthreads();

    const float scale = 0.125f;
    for (int p = tid; p < L_ * (L_ / 4); p += blockDim.x) {
        int i  = p / (L_ / 4);
        int j4 = (p % (L_ / 4)) * 4;
        float s0 = 0.f, s1 = 0.f, s2 = 0.f, s3 = 0.f;
        #pragma unroll 8
        for (int e = 0; e < DK_; ++e) {
            float qv = qs[i * DK_ + e];
            const float4 kv = *reinterpret_cast<const float4*>(kst + e * L_ + j4);
            s0 = fmaf(qv, kv.x, s0);
            s1 = fmaf(qv, kv.y, s1);
            s2 = fmaf(qv, kv.z, s2);
            s3 = fmaf(qv, kv.w, s3);
        }
        *reinterpret_cast<float4*>(S + i * S_STRIDE + j4) =
            make_float4(s0 * scale, s1 * scale, s2 * scale, s3 * scale);
    }
    __syncthreads();

    float* vs = kst;
    for (int idx = tid; idx < L_ * DK_; idx += blockDim.x) {
        int r = idx / DK_, e = idx % DK_;
        vs[r * DK_ + e] = vb[(size_t)r * D_ + e];
    }
    {
        int warp = tid >> 5, lane = tid & 31;
        for (int i = warp; i < L_; i += (int)(blockDim.x >> 5)) {
            float* Sr = S + i * S_STRIDE;
            float m = -1e30f;
            for (int j = lane; j < L_; j += 32) m = fmaxf(m, Sr[j]);
            #pragma unroll
            for (int off = 16; off; off >>= 1)
                m = fmaxf(m, __shfl_xor_sync(0xffffffff, m, off));
            float sum = 0.f;
            for (int j = lane; j < L_; j += 32) {
                float ev = __expf(Sr[j] - m);
                Sr[j] = ev;
                sum += ev;
            }
            #pragma unroll
            for (int off = 16; off; off >>= 1)
                sum += __shfl_xor_sync(0xffffffff, sum, off);
            float inv = 1.f / sum;
            for (int j = lane; j < L_; j += 32) Sr[j] *= inv;
        }
    }
    __syncthreads();

    for (int idx = tid; idx < L_ * DK_; idx += blockDim.x) {
        int i = idx / DK_, d = idx % DK_;
        const float* Sr = S + i * S_STRIDE;
        float acc = 0.f;
        #pragma unroll 4
        for (int j = 0; j < L_; ++j)
            acc = fmaf(Sr[j], vs[j * DK_ + d], acc);
        ob[(size_t)i * D_ + d] = acc;
    }
}

// ---------------- host-side launch helper -----------------------------------
static void mgemm(const float* A, const float* W, const float* bias, float* C,
                  int M, int N, int K, int mode, const float* pe = nullptr) {
    if (N > 64) {
        dim3 grid((N + 127) / 128, M / 128);
        switch (mode) {
            case 0: mma_gemm<128, 0><<<grid, 256>>>(M, N, K, A, W, bias, C, nullptr); break;
            case 1: mma_gemm<128, 1><<<grid, 256>>>(M, N, K, A, W, bias, C, nullptr); break;
            case 2: mma_gemm<128, 2><<<grid, 256>>>(M, N, K, A, W, bias, C, nullptr); break;
            default: mma_gemm<128, 3><<<grid, 256>>>(M, N, K, A, W, bias, C, pe);     break;
        }
    } else {
        dim3 grid((N + 63) / 64, M / 128);
        switch (mode) {
            case 0: mma_gemm<64, 0><<<grid, 256>>>(M, N, K, A, W, bias, C, nullptr); break;
            case 1: mma_gemm<64, 1><<<grid, 256>>>(M, N, K, A, W, bias, C, nullptr); break;
            case 2: mma_gemm<64, 2><<<grid, 256>>>(M, N, K, A, W, bias, C, nullptr); break;
            default: mma_gemm<64, 3><<<grid, 256>>>(M, N, K, A, W, bias, C, pe);     break;
        }
    }
}

extern "C" void kernel_launch(void* const* d_in, const int* in_sizes, int n_in,
                              void* d_out, int out_size) {
    (void)in_sizes; (void)n_in; (void)out_size;
    const float* x     = (const float*)d_in[0];
    const float* tok_w = (const float*)d_in[1];
    const float* pe    = (const float*)d_in[2];
    const float* Wq    = (const float*)d_in[3];
    const float* bq    = (const float*)d_in[4];
    const float* Wk    = (const float*)d_in[5];
    const float* bk    = (const float*)d_in[6];
    const float* Wv    = (const float*)d_in[7];
    const float* bv    = (const float*)d_in[8];
    // d_in[9]/d_in[10] (Wsig/bsig): prior branch never reaches output -> skipped
    const float* Wo    = (const float*)d_in[11];
    const float* bo    = (const float*)d_in[12];
    const float* W1    = (const float*)d_in[13];
    const float* b1    = (const float*)d_in[14];
    const float* W2    = (const float*)d_in[15];
    const float* b2    = (const float*)d_in[16];
    const float* pw    = (const float*)d_in[17];
    const float* pb    = (const float*)d_in[18];
    float* out = (float*)d_out;

    float *h, *q, *k, *v, *o, *y, *xg, *wp;
    cudaGetSymbolAddress((void**)&h,  g_h);
    cudaGetSymbolAddress((void**)&q,  g_q);
    cudaGetSymbolAddress((void**)&k,  g_k);
    cudaGetSymbolAddress((void**)&v,  g_v);
    cudaGetSymbolAddress((void**)&o,  g_o);
    cudaGetSymbolAddress((void**)&y,  g_y);
    cudaGetSymbolAddress((void**)&xg, g_xg);
    cudaGetSymbolAddress((void**)&wp, g_wp);

    cudaFuncSetAttribute(attn_kernel,
                         cudaFuncAttributeMaxDynamicSharedMemorySize,
                         ATTN_SMEM_BYTES);

    // token embedding: padded im2col gather + tok_w repack + GEMM (+PE epilogue)
    gather_kernel<<<(BL_ * KCP_ + 255) / 256, 256>>>(x);
    packw_kernel<<<(D_ * KCP_ + 255) / 256, 256>>>(tok_w);
    mgemm(xg, wp, nullptr, h, BL_, D_, KCP_, 3, pe);

    for (int l = 0; l < NL_; ++l) {
        const size_t wOff = (size_t)l * D_ * D_;
        mgemm(h, Wq + wOff, bq + (size_t)l * D_, q, BL_, D_, D_, 0);
        mgemm(h, Wk + wOff, bk + (size_t)l * D_, k, BL_, D_, D_, 0);
        mgemm(h, Wv + wOff, bv + (size_t)l * D_, v, BL_, D_, D_, 0);

        attn_kernel<<<B_ * H_, 256, ATTN_SMEM_BYTES>>>(q, k, v, o);

        mgemm(o, Wo + wOff, bo + (size_t)l * D_, h, BL_, D_, D_, 1);
        mgemm(h, W1 + (size_t)l * DFF_ * D_, b1 + (size_t)l * DFF_,
              y, BL_, DFF_, D_, 2);
        mgemm(y, W2 + (size_t)l * D_ * DFF_, b2 + (size_t)l * D_,
              h, BL_, D_, DFF_, 1);
    }

    mgemm(h, pw, pb, out, BL_, C_, D_, 0);
}